// round 15
// baseline (speedup 1.0000x reference)
#include <cuda_runtime.h>
#include <cuda_fp16.h>

// Problem constants
#define Bn 2
#define Ln 16
#define Cn 16
#define Hn 64
#define Wn 64
#define HW (Hn * Wn)            // 4096

// Padded transposed image, fp16: entry = 16 channels (32B).
// Rows cover y = -1..65 (PR=67), cols cover x = -1..64 (PC=66).
// Border entries are never written -> stay zero (device globals zero-init).
#define PR 67
#define PC 66
#define PLANE (PR * PC)         // 4422 entries per (b,l)

__device__ __half g_imgTh[Bn * Ln * PLANE * Cn];   // ~4.5 MB

static __device__ __forceinline__ unsigned pack_h2(float a, float b) {
    __half2 h = __floats2half2_rn(a, b);
    return *reinterpret_cast<unsigned*>(&h);
}

static __device__ __forceinline__ float4 ld_half4(const __half* p) {
    uint2 u = *reinterpret_cast<const uint2*>(p);
    __half2 h0 = *reinterpret_cast<const __half2*>(&u.x);
    __half2 h1 = *reinterpret_cast<const __half2*>(&u.y);
    float2 f0 = __half22float2(h0);
    float2 f1 = __half22float2(h1);
    return make_float4(f0.x, f0.y, f1.x, f1.y);
}

// ---------------------------------------------------------------------------
// Kernel 1: transpose images (B,L,C,H,W) -> padded fp16 (B,L,y,x,C).
// One thread per pixel: 16 coalesced float loads, 2 uint4 stores (32B).
// ---------------------------------------------------------------------------
__global__ void __launch_bounds__(256) transpose_kernel(const float* __restrict__ images) {
    int t = blockIdx.x * blockDim.x + threadIdx.x;   // 0 .. B*L*HW-1
    if (t >= Bn * Ln * HW) return;
    int hw = t & (HW - 1);
    int bl = t >> 12;
    int w = hw & (Wn - 1);
    int h = hw >> 6;

    const float* src = images + (size_t)bl * Cn * HW + hw;
    float v[Cn];
#pragma unroll
    for (int c = 0; c < Cn; c++) v[c] = src[(size_t)c * HW];

    size_t e = (size_t)bl * PLANE + (size_t)(h + 1) * PC + (w + 1);
    uint4* dst = reinterpret_cast<uint4*>(g_imgTh + e * Cn);
    dst[0] = make_uint4(pack_h2(v[0], v[1]),  pack_h2(v[2], v[3]),
                        pack_h2(v[4], v[5]),  pack_h2(v[6], v[7]));
    dst[1] = make_uint4(pack_h2(v[8], v[9]),  pack_h2(v[10], v[11]),
                        pack_h2(v[12], v[13]), pack_h2(v[14], v[15]));
}

// ---------------------------------------------------------------------------
// Kernel 2: main. Same sampling loop as round-14 (4 lanes/pixel, serial flow
// chain, unroll 2). NEW: perfectly uniform block workload — each 128-thread
// block owns a 32-pixel tile and processes BOTH i = i8 and i = 15-i8 for it:
// (i8+1) + (16-i8) = 17 j-samples per block, identical for all 2048 blocks.
// Removes the 16x duration spread that limited the schedule.
// ---------------------------------------------------------------------------
__global__ void __launch_bounds__(128) gridsample_pscan_kernel(const float* __restrict__ flows,
                                                               float* __restrict__ out) {
    const int bid = blockIdx.x;            // 0 .. 2047
    const int hwt = bid & 127;             // 128 pixel-tiles of 32 pixels
    const int q   = bid >> 7;              // 0 .. 15
    const int b   = q & 1;
    const int i8  = q >> 1;                // 0 .. 7
    const int tid = threadIdx.x;
    const int cg  = tid & 3;               // channel group (4 channels)
    const int hw  = (hwt << 5) | (tid >> 2);
    const int w   = hw & (Wn - 1);
    const int h   = hw >> 6;

    const float uxb = (float)w + 0.5f;
    const float fyb = (float)h;

    const float* flowb = flows + (size_t)b * Ln * 2 * HW + hw;     // + (j*2+d)*HW
    const __half* imgb = g_imgTh + (size_t)b * Ln * PLANE * Cn + cg * 4;

#pragma unroll
    for (int ph = 0; ph < 2; ph++) {
        const int i = ph ? (15 - i8) : i8;

        float relx = 0.0f, rely = 0.0f;   // cum_i - cum_j ; zero at j = i
        float acc0 = 0.0f, acc1 = 0.0f, acc2 = 0.0f, acc3 = 0.0f;

#pragma unroll 2
        for (int j = i; j >= 0; --j) {
            // x: wrap into [0,64), then shift by -0.5
            float u  = fmaf(relx, 32.0f, uxb);
            float fq = floorf(u * 0.015625f);           // u/64
            float ix = fmaf(fq, -64.0f, u) - 0.5f;      // in [-0.5, 63.5)
            // y: clamp to [-1, 64] (== reference masking w/ zero border)
            float iy = fmaf(rely, 32.0f, fyb);
            iy = fminf(fmaxf(iy, -1.0f), 64.0f);

            float x0f = floorf(ix), y0f = floorf(iy);
            float wx = ix - x0f,    wy = iy - y0f;
            int x0 = (int)x0f, y0 = (int)y0f;           // x0 in [-1,63], y0 in [-1,64]

            float wx1 = 1.0f - wx, wy1 = 1.0f - wy;
            float w00 = wx1 * wy1, w01 = wx * wy1, w10 = wx1 * wy, w11 = wx * wy;

            // entry index: j*PLANE + (y0+1)*PC + (x0+1) -> always in-bounds
            int e = j * PLANE + y0 * PC + x0 + (PC + 1);
            const __half* p = imgb + ((size_t)e << 4);   // e * 16 halves

            const float4 v00 = ld_half4(p);
            const float4 v01 = ld_half4(p + Cn);
            const float4 v10 = ld_half4(p + PC * Cn);
            const float4 v11 = ld_half4(p + (PC + 1) * Cn);

            acc0 += w00 * v00.x + w01 * v01.x + w10 * v10.x + w11 * v11.x;
            acc1 += w00 * v00.y + w01 * v01.y + w10 * v10.y + w11 * v11.y;
            acc2 += w00 * v00.z + w01 * v01.z + w10 * v10.z + w11 * v11.z;
            acc3 += w00 * v00.w + w01 * v01.w + w10 * v10.w + w11 * v11.w;

            // advance rel to (i, j-1): rel += flow[j]
            relx += flowb[(size_t)(j * 2 + 0) * HW];
            rely += flowb[(size_t)(j * 2 + 1) * HW];
        }

        // out[b,i,c,h,w]: this lane owns channels 4*cg .. 4*cg+3
        const int bi = (b << 4) | i;
        float* op = out + (size_t)bi * Cn * HW + (size_t)(cg * 4) * HW + hw;
        op[0 * HW] = acc0;
        op[1 * HW] = acc1;
        op[2 * HW] = acc2;
        op[3 * HW] = acc3;
    }
}

extern "C" void kernel_launch(void* const* d_in, const int* in_sizes, int n_in,
                              void* d_out, int out_size) {
    const float* flows  = (const float*)d_in[0];   // (B,L,2,H,W)
    const float* images = (const float*)d_in[1];   // (B,L,C,H,W)
    float* out = (float*)d_out;                    // (B,L,C,H,W)

    const int nT = Bn * Ln * HW;           // 131072 transpose threads
    transpose_kernel<<<(nT + 255) / 256, 256>>>(images);

    gridsample_pscan_kernel<<<2048, 128>>>(flows, out);
}

// round 16
// speedup vs baseline: 1.8499x; 1.8499x over previous
#include <cuda_runtime.h>
#include <cuda_fp16.h>

// Problem constants
#define Bn 2
#define Ln 16
#define Cn 16
#define Hn 64
#define Wn 64
#define HW (Hn * Wn)            // 4096

// Padded transposed image, fp16: entry = 16 channels (32B).
// Rows cover y = -1..65 (PR=67), cols cover x = -1..64 (PC=66).
// Border entries are never written -> stay zero (device globals zero-init).
#define PR 67
#define PC 66
#define PLANE (PR * PC)         // 4422 entries per (b,l)

__device__ __half g_imgTh[Bn * Ln * PLANE * Cn];   // ~4.5 MB

static __device__ __forceinline__ unsigned pack_h2(float a, float b) {
    __half2 h = __floats2half2_rn(a, b);
    return *reinterpret_cast<unsigned*>(&h);
}

static __device__ __forceinline__ __half2 as_h2(unsigned u) {
    return *reinterpret_cast<const __half2*>(&u);
}

// ---------------------------------------------------------------------------
// Kernel 1: transpose images (B,L,C,H,W) -> padded fp16 (B,L,y,x,C).
// One thread per 8-channel half-pixel: 8 coalesced float loads, 1 uint4 store.
// 2x threads vs previous version -> better latency hiding (kernel is
// sub-one-wave / latency-bound).
// ---------------------------------------------------------------------------
__global__ void __launch_bounds__(256) transpose_kernel(const float* __restrict__ images) {
    int t = blockIdx.x * blockDim.x + threadIdx.x;   // 0 .. 2*B*L*HW-1
    if (t >= 2 * Bn * Ln * HW) return;
    int half_id = t & 1;            // which 8 channels
    int pix = t >> 1;
    int hw = pix & (HW - 1);
    int bl = pix >> 12;
    int w = hw & (Wn - 1);
    int h = hw >> 6;

    const float* src = images + (size_t)bl * Cn * HW + (size_t)(half_id * 8) * HW + hw;
    float v[8];
#pragma unroll
    for (int c = 0; c < 8; c++) v[c] = src[(size_t)c * HW];

    size_t e = (size_t)bl * PLANE + (size_t)(h + 1) * PC + (w + 1);
    uint4* dst = reinterpret_cast<uint4*>(g_imgTh + e * Cn) + half_id;
    *dst = make_uint4(pack_h2(v[0], v[1]), pack_h2(v[2], v[3]),
                      pack_h2(v[4], v[5]), pack_h2(v[6], v[7]));
}

// ---------------------------------------------------------------------------
// Kernel 2: main (round-14 structure frozen: 4 lanes/pixel, serial flow
// chain, unroll 2, LPT block order). NEW: bilinear blend done in packed
// half2 (HMUL2/HFMA2), converted to fp32 once per j for accumulation —
// cuts interpolation math from 32 to 20 warp-instructions per j.
// ---------------------------------------------------------------------------
__global__ void __launch_bounds__(256) gridsample_pscan_kernel(const float* __restrict__ flows,
                                                               float* __restrict__ out) {
    const int bid = blockIdx.x;            // 0 .. 2047
    const int q   = bid >> 6;              // 0 .. 31
    const int b   = q & 1;
    const int i   = 15 - (q >> 1);         // heavy blocks first (LPT)
    const int tid = threadIdx.x;
    const int cg  = tid & 3;               // channel group (4 channels)
    const int hw  = ((bid & 63) << 6) | (tid >> 2);
    const int w   = hw & (Wn - 1);
    const int h   = hw >> 6;
    const int bi  = (b << 4) | i;          // for output addressing

    const float uxb = (float)w + 0.5f;
    const float fyb = (float)h;

    const float* flowb = flows + (size_t)b * Ln * 2 * HW + hw;     // + (j*2+d)*HW
    const __half* imgb = g_imgTh + (size_t)b * Ln * PLANE * Cn + cg * 4;

    float relx = 0.0f, rely = 0.0f;   // cum_i - cum_j ; zero at j = i
    float acc0 = 0.0f, acc1 = 0.0f, acc2 = 0.0f, acc3 = 0.0f;

#pragma unroll 2
    for (int j = i; j >= 0; --j) {
        // x: wrap into [0,64), then shift by -0.5
        float u  = fmaf(relx, 32.0f, uxb);
        float fq = floorf(u * 0.015625f);           // u/64
        float ix = fmaf(fq, -64.0f, u) - 0.5f;      // in [-0.5, 63.5)
        // y: clamp to [-1, 64] (== reference masking w/ zero border)
        float iy = fmaf(rely, 32.0f, fyb);
        iy = fminf(fmaxf(iy, -1.0f), 64.0f);

        float x0f = floorf(ix), y0f = floorf(iy);
        float wx = ix - x0f,    wy = iy - y0f;
        int x0 = (int)x0f, y0 = (int)y0f;           // x0 in [-1,63], y0 in [-1,64]

        float wx1 = 1.0f - wx, wy1 = 1.0f - wy;
        const __half2 W00 = __float2half2_rn(wx1 * wy1);
        const __half2 W01 = __float2half2_rn(wx * wy1);
        const __half2 W10 = __float2half2_rn(wx1 * wy);
        const __half2 W11 = __float2half2_rn(wx * wy);

        // entry index: j*PLANE + (y0+1)*PC + (x0+1) -> always in-bounds
        int e = j * PLANE + y0 * PC + x0 + (PC + 1);
        const __half* p = imgb + ((size_t)e << 4);   // e * 16 halves

        const uint2 u00 = *reinterpret_cast<const uint2*>(p);
        const uint2 u01 = *reinterpret_cast<const uint2*>(p + Cn);
        const uint2 u10 = *reinterpret_cast<const uint2*>(p + PC * Cn);
        const uint2 u11 = *reinterpret_cast<const uint2*>(p + (PC + 1) * Cn);

        // packed bilinear blend: channels {0,1} and {2,3}
        __half2 ra = __hmul2(as_h2(u00.x), W00);
        ra = __hfma2(as_h2(u01.x), W01, ra);
        ra = __hfma2(as_h2(u10.x), W10, ra);
        ra = __hfma2(as_h2(u11.x), W11, ra);
        __half2 rb = __hmul2(as_h2(u00.y), W00);
        rb = __hfma2(as_h2(u01.y), W01, rb);
        rb = __hfma2(as_h2(u10.y), W10, rb);
        rb = __hfma2(as_h2(u11.y), W11, rb);

        float2 fa = __half22float2(ra);
        float2 fb = __half22float2(rb);
        acc0 += fa.x;
        acc1 += fa.y;
        acc2 += fb.x;
        acc3 += fb.y;

        // advance rel to (i, j-1): rel += flow[j]
        relx += flowb[(size_t)(j * 2 + 0) * HW];
        rely += flowb[(size_t)(j * 2 + 1) * HW];
    }

    // out[b,i,c,h,w]: this lane owns channels 4*cg .. 4*cg+3
    float* op = out + (size_t)bi * Cn * HW + (size_t)(cg * 4) * HW + hw;
    op[0 * HW] = acc0;
    op[1 * HW] = acc1;
    op[2 * HW] = acc2;
    op[3 * HW] = acc3;
}

extern "C" void kernel_launch(void* const* d_in, const int* in_sizes, int n_in,
                              void* d_out, int out_size) {
    const float* flows  = (const float*)d_in[0];   // (B,L,2,H,W)
    const float* images = (const float*)d_in[1];   // (B,L,C,H,W)
    float* out = (float*)d_out;                    // (B,L,C,H,W)

    const int nT = 2 * Bn * Ln * HW;       // 262144 transpose threads
    transpose_kernel<<<(nT + 255) / 256, 256>>>(images);

    gridsample_pscan_kernel<<<2048, 256>>>(flows, out);
}